// round 1
// baseline (speedup 1.0000x reference)
#include <cuda_runtime.h>
#include <math.h>

#define BB 8
#define TT 200
#define UU 50
#define VV 1024

// Scratch: normalized log-probs, layout [b][u][t] (t contiguous for coalesced
// phase-1 writes and conflict-free phase-2 smem access).
__device__ float g_blank[BB * UU * TT];          // blank[b][u][t]
__device__ float g_emit [BB * (UU - 1) * TT];    // emit [b][u][t]

// ---------------------------------------------------------------------------
// Phase 1: for each (b,u) compute LSE over t of h[b,t,u,0] and h[b,t,u,tgt],
// write blank/emit = h - lse. One block per (b,u); threads 0..127 handle the
// blank column (v=0), threads 128..255 the emit column (v=targets[b][u]).
// ---------------------------------------------------------------------------
__global__ void __launch_bounds__(256)
lse_gather_kernel(const float* __restrict__ h,
                  const int* __restrict__ targets,
                  float* __restrict__ out) {
    int bu = blockIdx.x;
    int b = bu / UU, u = bu % UU;
    int tid = threadIdx.x;

    if (bu == 0 && tid == 0) *out = 0.0f;  // zero the (poisoned) output before phase 2

    int half = tid >> 7;      // 0 = blank column, 1 = emit column
    int lane = tid & 127;

    bool active = true;
    int v = 0;
    if (half == 1) {
        if (u >= UU - 1) active = false;      // no emit column at u = U-1
        else v = targets[b * (UU - 1) + u];
    }

    // h[((b*T + t)*U + u)*V + v], t stride = U*V
    const float* base = h + (size_t)b * TT * UU * VV + (size_t)u * VV + v;

    float x0 = -INFINITY, x1 = -INFINITY;
    if (active) {
        x0 = base[(size_t)lane * (UU * VV)];                  // t = lane (< 128 < T)
        if (lane + 128 < TT) x1 = base[(size_t)(lane + 128) * (UU * VV)];
    }

    __shared__ float sh[256];

    // max reduction per 128-thread half
    sh[tid] = fmaxf(x0, x1);
    for (int s = 64; s > 0; s >>= 1) {
        __syncthreads();
        if (lane < s) sh[tid] = fmaxf(sh[tid], sh[tid + s]);
    }
    __syncthreads();
    float mx = sh[half << 7];
    __syncthreads();

    // sum of exp(x - max) per half
    float e = 0.0f;
    if (active) {
        e = __expf(x0 - mx);
        if (lane + 128 < TT) e += __expf(x1 - mx);
    }
    sh[tid] = e;
    for (int s = 64; s > 0; s >>= 1) {
        __syncthreads();
        if (lane < s) sh[tid] += sh[tid + s];
    }
    __syncthreads();
    float lse = mx + __logf(sh[half << 7]);

    if (active) {
        float* dst = (half == 0) ? (g_blank + (b * UU + u) * TT)
                                 : (g_emit  + (b * (UU - 1) + u) * TT);
        dst[lane] = x0 - lse;
        if (lane + 128 < TT) dst[lane + 128] = x1 - lse;
    }
}

// ---------------------------------------------------------------------------
// Phase 2: RNN-T forward DP per batch, anti-diagonal wavefront.
//   alpha[0][0] = 0
//   alpha[0][j] = alpha[0][j-1] + emit[0][j-1]
//   alpha[t][0] = alpha[t-1][0] + blank[t-1][0]
//   alpha[t][j] = logaddexp(alpha[t-1][j] + blank[t-1][j],
//                           alpha[t][j-1] + emit[t][j-1])
// Thread j owns column j: alpha[t-1][j] lives in a register; alpha[t][j-1]
// crosses threads via a double-buffered smem diagonal (1 barrier / diagonal).
// ---------------------------------------------------------------------------
__global__ void __launch_bounds__(128)
rnnt_dp_kernel(const int* __restrict__ input_lens,
               const int* __restrict__ target_lens,
               float* __restrict__ out) {
    extern __shared__ float sm[];
    float* sb = sm;               // blank[u][t], UU*TT floats
    float* se = sm + UU * TT;     // emit [u][t], (UU-1)*TT floats

    int b = blockIdx.x;
    int tid = threadIdx.x;

    // Stage blank/emit for this batch into shared memory (float4, coalesced).
    {
        const float4* srcb = (const float4*)(g_blank + b * (UU * TT));
        const float4* srce = (const float4*)(g_emit  + b * ((UU - 1) * TT));
        float4* db = (float4*)sb;
        float4* de = (float4*)se;
        for (int i = tid; i < (UU * TT) / 4; i += 128) db[i] = srcb[i];
        for (int i = tid; i < ((UU - 1) * TT) / 4; i += 128) de[i] = srce[i];
    }
    __syncthreads();

    int ti = input_lens[b] - 1;
    int ui = target_lens[b] - 1;

    __shared__ float dbuf[2][64];

    int j = tid;                  // column owned by this thread (active if j < UU)
    float own = 0.0f;             // alpha[t-1][j]
    float final_val = 0.0f;

    for (int d = 0; d < TT + UU - 1; ++d) {
        int t = d - j;
        if (j < UU && t >= 0 && t < TT) {
            float nv;
            if (t == 0) {
                nv = (j == 0) ? 0.0f
                              : dbuf[(d & 1) ^ 1][j - 1] + se[(j - 1) * TT];
            } else if (j == 0) {
                nv = own + sb[t - 1];
            } else {
                float x = own + sb[j * TT + (t - 1)];
                float y = dbuf[(d & 1) ^ 1][j - 1] + se[(j - 1) * TT + t];
                float m = fmaxf(x, y);
                nv = m + log1pf(__expf(-fabsf(x - y)));
            }
            dbuf[d & 1][j] = nv;
            own = nv;
            if (t == ti && j == ui) final_val = nv;
        }
        __syncthreads();
    }

    if (j == ui) {
        float loss = final_val + sb[ui * TT + ti];   // + blank[b][ti][ui]
        atomicAdd(out, -loss * (1.0f / BB));
    }
}

// ---------------------------------------------------------------------------
extern "C" void kernel_launch(void* const* d_in, const int* in_sizes, int n_in,
                              void* d_out, int out_size) {
    const float* h           = (const float*)d_in[0];
    const int*   targets     = (const int*)d_in[1];
    const int*   input_lens  = (const int*)d_in[2];
    const int*   target_lens = (const int*)d_in[3];
    float* out = (float*)d_out;

    size_t smem = (size_t)(UU * TT + (UU - 1) * TT) * sizeof(float);  // 79200 B
    cudaFuncSetAttribute(rnnt_dp_kernel,
                         cudaFuncAttributeMaxDynamicSharedMemorySize, (int)smem);

    lse_gather_kernel<<<BB * UU, 256>>>(h, targets, out);
    rnnt_dp_kernel<<<BB, 128, smem>>>(input_lens, target_lens, out);
}

// round 2
// speedup vs baseline: 1.5719x; 1.5719x over previous
#include <cuda_runtime.h>
#include <math.h>

#define BB 8
#define TT 200
#define UU 50
#define VV 1024

#define INV_LN2 1.4426950408889634f
#define LN2     0.6931471805599453f

__device__ __forceinline__ float ex2f(float x) {
    float r; asm("ex2.approx.f32 %0, %1;" : "=f"(r) : "f"(x)); return r;
}
__device__ __forceinline__ float lg2f(float x) {
    float r; asm("lg2.approx.f32 %0, %1;" : "=f"(r) : "f"(x)); return r;
}
__device__ __forceinline__ float logadd2(float x, float y) {
    // log2-domain logaddexp: max + log2(1 + 2^(-|x-y|)); -inf inputs handled by ex2(-inf)=0
    float m = fmaxf(x, y);
    float d = fabsf(x - y);
    return m + lg2f(1.0f + ex2f(-d));
}

#define NEG_INF __int_as_float(0xff800000)

// Scratch: log2-domain normalized log-probs, layout [b][u][t].
__device__ float g_blank[BB * UU * TT];          // blank2[b][u][t]
__device__ float g_emit [BB * (UU - 1) * TT];    // emit2 [b][u][t]

// ---------------------------------------------------------------------------
// Phase 1: barrier-free. One warp per column. Block = (b,u); warp 0 handles
// the blank column (v=0), warp 1 the emit column (v=targets[b][u]).
// Output already in log2 domain: (h - lse)/ln2.
// ---------------------------------------------------------------------------
__global__ void __launch_bounds__(64)
lse_gather_kernel(const float* __restrict__ h,
                  const int* __restrict__ targets,
                  float* __restrict__ out) {
    int bu = blockIdx.x;
    int b = bu / UU, u = bu % UU;
    int w = threadIdx.x >> 5, lane = threadIdx.x & 31;

    if (bu == 0 && threadIdx.x == 0) *out = 0.0f;   // output is poisoned; zero it

    if (w == 1 && u >= UU - 1) return;              // no emit column at u = U-1
    int v = (w == 1) ? targets[b * (UU - 1) + u] : 0;

    // h[((b*T + t)*U + u)*V + v], t-stride = U*V
    const float* base = h + (size_t)b * TT * UU * VV + (size_t)u * VV + v;

    float x[7];
#pragma unroll
    for (int i = 0; i < 7; ++i) {
        int t = lane + 32 * i;
        x[i] = (t < TT) ? base[(size_t)t * (UU * VV)] * INV_LN2 : NEG_INF;
    }

    float m = x[0];
#pragma unroll
    for (int i = 1; i < 7; ++i) m = fmaxf(m, x[i]);
#pragma unroll
    for (int o = 16; o > 0; o >>= 1) m = fmaxf(m, __shfl_xor_sync(0xffffffffu, m, o));

    float s = 0.0f;
#pragma unroll
    for (int i = 0; i < 7; ++i) s += ex2f(x[i] - m);   // ex2(-inf)=0 for padded slots
#pragma unroll
    for (int o = 16; o > 0; o >>= 1) s += __shfl_xor_sync(0xffffffffu, s, o);

    float lse = m + lg2f(s);

    float* dst = (w == 0) ? (g_blank + (b * UU + u) * TT)
                          : (g_emit  + (b * (UU - 1) + u) * TT);
#pragma unroll
    for (int i = 0; i < 7; ++i) {
        int t = lane + 32 * i;
        if (t < TT) dst[t] = x[i] - lse;
    }
}

// ---------------------------------------------------------------------------
// Phase 2: RNN-T forward DP, single-warp wavefront per batch (no barriers in
// the DP loop). Lane k owns columns jA=2k, jB=2k+1 (k<25). At step d, lane k
// processes t = d - k: col A needs alpha[t][2k-1] from lane k-1's previous
// step (shfl_up of its col-B value); col B chains off col A in-thread.
// alpha[t-1][*] live in registers; blank/emit staged in smem (conflict-free:
// lane stride 399 = 15 mod 32, gcd(15,32)=1).
// ---------------------------------------------------------------------------
__global__ void __launch_bounds__(128)
rnnt_dp_kernel(const int* __restrict__ input_lens,
               const int* __restrict__ target_lens,
               float* __restrict__ out) {
    extern __shared__ float sm[];
    float* sb = sm;               // blank2[u][t], UU*TT
    float* se = sm + UU * TT;     // emit2 [u][t], (UU-1)*TT

    int b = blockIdx.x;
    int tid = threadIdx.x;

    // Stage with all 128 threads (float4, coalesced).
    {
        const float4* srcb = (const float4*)(g_blank + b * (UU * TT));
        const float4* srce = (const float4*)(g_emit  + b * ((UU - 1) * TT));
        float4* db = (float4*)sb;
        float4* de = (float4*)se;
#pragma unroll 4
        for (int i = tid; i < (UU * TT) / 4; i += 128) db[i] = srcb[i];
#pragma unroll 4
        for (int i = tid; i < ((UU - 1) * TT) / 4; i += 128) de[i] = srce[i];
    }
    __syncthreads();
    if (tid >= 32) return;        // DP runs in warp 0 only

    int ti = input_lens[b] - 1;
    int ui = target_lens[b] - 1;

    int k = tid;
    int jA = 2 * k, jB = 2 * k + 1;
    bool th_act = (jA < UU);      // k < 25

    float own0 = 0.0f, own1 = 0.0f;   // alpha[t-1][jA], alpha[t-1][jB]
    float fin = 0.0f;

    const float* sbA = sb + jA * TT;
    const float* sbB = sb + jB * TT;
    const float* seA = se + (jA - 1) * TT;   // emit col jA-1 (unused for k==0)
    const float* seB = se + jA * TT;         // emit col jB-1 = jA

    for (int d = 0; d < TT + UU / 2 - 1; ++d) {
        float prev = __shfl_up_sync(0xffffffffu, own1, 1);  // alpha[t][jA-1]
        int t = d - k;
        if (th_act && t >= 0 && t < TT) {
            // column jA
            float x = (t > 0) ? own0 + sbA[t - 1] : NEG_INF;
            float y = (k > 0) ? prev + seA[t]     : NEG_INF;
            float nvA = logadd2(x, y);
            if (t == 0 && k == 0) nvA = 0.0f;
            // column jB (depends on nvA)
            float xB = (t > 0) ? own1 + sbB[t - 1] : NEG_INF;
            float yB = nvA + seB[t];
            float nvB = logadd2(xB, yB);
            own0 = nvA; own1 = nvB;
            if (t == ti) {
                if (jA == ui) fin = nvA;
                if (jB == ui) fin = nvB;
            }
        }
    }

    bool holds = th_act && (jA == ui || jB == ui);
    if (holds) {
        float loss2 = fin + sb[ui * TT + ti];         // + blank2[ti][ui]
        atomicAdd(out, -loss2 * LN2 * (1.0f / BB));
    }
}

// ---------------------------------------------------------------------------
extern "C" void kernel_launch(void* const* d_in, const int* in_sizes, int n_in,
                              void* d_out, int out_size) {
    const float* h           = (const float*)d_in[0];
    const int*   targets     = (const int*)d_in[1];
    const int*   input_lens  = (const int*)d_in[2];
    const int*   target_lens = (const int*)d_in[3];
    float* out = (float*)d_out;

    size_t smem = (size_t)(UU * TT + (UU - 1) * TT) * sizeof(float);  // 79200 B
    cudaFuncSetAttribute(rnnt_dp_kernel,
                         cudaFuncAttributeMaxDynamicSharedMemorySize, (int)smem);

    lse_gather_kernel<<<BB * UU, 64>>>(h, targets, out);
    rnnt_dp_kernel<<<BB, 128, smem>>>(input_lens, target_lens, out);
}

// round 3
// speedup vs baseline: 1.6468x; 1.0477x over previous
#include <cuda_runtime.h>
#include <math.h>

#define BB 8
#define TT 200
#define UU 50
#define VV 1024
#define TTP 201            // smem row stride: 201 % 32 = 9, gcd(9,32)=1 -> conflict-free

#define INV_LN2 1.4426950408889634f
#define LN2     0.6931471805599453f
#define NEG_INF __int_as_float(0xff800000)

__device__ __forceinline__ float ex2f(float x) {
    float r; asm("ex2.approx.f32 %0, %1;" : "=f"(r) : "f"(x)); return r;
}
__device__ __forceinline__ float lg2f(float x) {
    float r; asm("lg2.approx.f32 %0, %1;" : "=f"(r) : "f"(x)); return r;
}
__device__ __forceinline__ float logadd2(float x, float y) {
    float m = fmaxf(x, y);
    float d = fabsf(x - y);
    return m + lg2f(1.0f + ex2f(-d));   // handles one-arm -inf: ex2(-inf)=0
}

// Scratch: log2-domain normalized log-probs, layout [b][u][t] (packed, t-contig).
__device__ float g_blank[BB * UU * TT];
__device__ float g_emit [BB * (UU - 1) * TT];

// ---------------------------------------------------------------------------
// Phase 1: one warp per (b,u,column). Warp 0 = blank (v=0), warp 1 = emit.
// Writes (h - lse)/ln2 (log2 domain).
// ---------------------------------------------------------------------------
__global__ void __launch_bounds__(64)
lse_gather_kernel(const float* __restrict__ h,
                  const int* __restrict__ targets,
                  float* __restrict__ out) {
    int bu = blockIdx.x;
    int b = bu / UU, u = bu % UU;
    int w = threadIdx.x >> 5, lane = threadIdx.x & 31;

    if (bu == 0 && threadIdx.x == 0) *out = 0.0f;

    if (w == 1 && u >= UU - 1) return;
    int v = (w == 1) ? targets[b * (UU - 1) + u] : 0;

    const float* base = h + (size_t)b * TT * UU * VV + (size_t)u * VV + v;

    float x[7];
#pragma unroll
    for (int i = 0; i < 7; ++i) {
        int t = lane + 32 * i;
        x[i] = (t < TT) ? base[(size_t)t * (UU * VV)] * INV_LN2 : NEG_INF;
    }

    float m = x[0];
#pragma unroll
    for (int i = 1; i < 7; ++i) m = fmaxf(m, x[i]);
#pragma unroll
    for (int o = 16; o > 0; o >>= 1) m = fmaxf(m, __shfl_xor_sync(0xffffffffu, m, o));

    float s = 0.0f;
#pragma unroll
    for (int i = 0; i < 7; ++i) s += ex2f(x[i] - m);
#pragma unroll
    for (int o = 16; o > 0; o >>= 1) s += __shfl_xor_sync(0xffffffffu, s, o);

    float lse = m + lg2f(s);

    float* dst = (w == 0) ? (g_blank + (b * UU + u) * TT)
                          : (g_emit  + (b * (UU - 1) + u) * TT);
#pragma unroll
    for (int i = 0; i < 7; ++i) {
        int t = lane + 32 * i;
        if (t < TT) dst[t] = x[i] - lse;
    }
}

// ---------------------------------------------------------------------------
// Phase 2: single-warp wavefront, lane k owns columns k (slot A) and k+32
// (slot B, k<18) on independent anti-diagonals (col j processed at step
// d = t + j). Per step: 2 shfls + 2 INDEPENDENT logadd2s (ILP). Branchless.
// ---------------------------------------------------------------------------
__global__ void __launch_bounds__(256)
rnnt_dp_kernel(const int* __restrict__ input_lens,
               const int* __restrict__ target_lens,
               float* __restrict__ out) {
    extern __shared__ float sm[];
    float* sb = sm;                 // blank2[u][t], 50 rows, stride TTP
    float* se = sm + UU * TTP;      // emit2 [u][t], 49 rows, stride TTP

    int b = blockIdx.x;
    int tid = threadIdx.x;

    // Stage (scalar, contiguous global reads; STS conflict-free within warps).
    {
        const float* srcb = g_blank + b * (UU * TT);
        const float* srce = g_emit  + b * ((UU - 1) * TT);
#pragma unroll 4
        for (int i = tid; i < UU * TT; i += 256) {
            int u = i / TT, t = i - u * TT;
            sb[u * TTP + t] = srcb[i];
        }
#pragma unroll 4
        for (int i = tid; i < (UU - 1) * TT; i += 256) {
            int u = i / TT, t = i - u * TT;
            se[u * TTP + t] = srce[i];
        }
    }
    __syncthreads();
    if (tid >= 32) return;

    int ti = input_lens[b] - 1;
    int ui = target_lens[b] - 1;

    int k = tid;
    int jB = 32 + k;

    // Row pointers (clamped so inactive lanes stay in bounds).
    const float* rowA_b = sb + k * TTP;
    const float* rowB_b = sb + min(jB, UU - 1) * TTP;
    const float* rowA_e = se + max(k - 1, 0) * TTP;          // emit col k-1 -> col k
    const float* rowB_e = se + min(jB - 1, UU - 2) * TTP;    // emit col jB-1 -> col jB

    float own0 = NEG_INF, own1 = NEG_INF;
    float fin = 0.0f;

#pragma unroll 2
    for (int d = 0; d < TT + UU - 1; ++d) {
        float prevA = __shfl_sync(0xffffffffu, own0, (k + 31) & 31);
        float prevB = __shfl_sync(0xffffffffu, own1, (k + 31) & 31);

        // slot A: column k, t = d - k
        int tA = d - k;
        int tAc = min(max(tA, 0), TT - 1);
        float xA = (tA > 0) ? own0 + rowA_b[max(tAc - 1, 0)] : NEG_INF;
        float yA = (k > 0) ? prevA + rowA_e[tAc] : NEG_INF;
        float nA = logadd2(xA, yA);
        nA = (tA == 0 && k == 0) ? 0.0f : nA;

        // slot B: column 32+k, t = tA - 32 (independent of slot A this step)
        int tB = tA - 32;
        int tBc = min(max(tB, 0), TT - 1);
        float xB = (tB > 0) ? own1 + rowB_b[max(tBc - 1, 0)] : NEG_INF;
        float pB = (k == 0) ? prevA : prevB;    // col 32's left neighbor = col 31 (lane 31 slot A)
        float yB = pB + rowB_e[tBc];
        float nB = logadd2(xB, yB);

        fin = (tA == ti && k  == ui) ? nA : fin;
        fin = (tB == ti && jB == ui) ? nB : fin;

        own0 = nA;
        own1 = nB;
    }

    bool holds = (k == ui) || (jB == ui && jB < UU);
    if (holds) {
        float loss2 = fin + sb[ui * TTP + ti];
        atomicAdd(out, -loss2 * LN2 * (1.0f / BB));
    }
}

// ---------------------------------------------------------------------------
extern "C" void kernel_launch(void* const* d_in, const int* in_sizes, int n_in,
                              void* d_out, int out_size) {
    const float* h           = (const float*)d_in[0];
    const int*   targets     = (const int*)d_in[1];
    const int*   input_lens  = (const int*)d_in[2];
    const int*   target_lens = (const int*)d_in[3];
    float* out = (float*)d_out;

    size_t smem = (size_t)(UU * TTP + (UU - 1) * TTP) * sizeof(float);  // 79596 B
    cudaFuncSetAttribute(rnnt_dp_kernel,
                         cudaFuncAttributeMaxDynamicSharedMemorySize, (int)smem);

    lse_gather_kernel<<<BB * UU, 64>>>(h, targets, out);
    rnnt_dp_kernel<<<BB, 256, smem>>>(input_lens, target_lens, out);
}

// round 4
// speedup vs baseline: 2.1217x; 1.2884x over previous
#include <cuda_runtime.h>
#include <math.h>

#define BB 8
#define TT 200
#define UU 50
#define VV 1024

#define FRONT 64                    // front pad (covers tB-1 down to -63)
#define BACK  49                    // back pad (covers tA up to 248)
#define RW    (FRONT + TT + BACK)   // 313; 313 % 32 = 25, gcd(25,32)=1 -> conflict-free
#define NROWS (UU + (UU - 1) + 1)   // 50 blank + 49 emit + 1 dummy = 100

#define INV_LN2 1.4426950408889634f
#define LN2     0.6931471805599453f
#define NEG_INF __int_as_float(0xff800000)
#define SENT    (-1.0e30f)

__device__ __forceinline__ float ex2f(float x) {
    float r; asm("ex2.approx.f32 %0, %1;" : "=f"(r) : "f"(x)); return r;
}
__device__ __forceinline__ float lg2f(float x) {
    float r; asm("lg2.approx.f32 %0, %1;" : "=f"(r) : "f"(x)); return r;
}
__device__ __forceinline__ float logadd2(float x, float y) {
    float e = ex2f(-fabsf(x - y));          // modifiers fold into MUFU input
    return fmaxf(x, y) + lg2f(1.0f + e);    // finite sentinels: e=0, lg2(1)=0
}

// Scratch: log2-domain normalized log-probs, layout [b][u][t] (packed).
__device__ float g_blank[BB * UU * TT];
__device__ float g_emit [BB * (UU - 1) * TT];

// ---------------------------------------------------------------------------
// Phase 1: one warp per (b,u,column). Warp 0 = blank (v=0), warp 1 = emit.
// ---------------------------------------------------------------------------
__global__ void __launch_bounds__(64)
lse_gather_kernel(const float* __restrict__ h,
                  const int* __restrict__ targets,
                  float* __restrict__ out) {
    int bu = blockIdx.x;
    int b = bu / UU, u = bu % UU;
    int w = threadIdx.x >> 5, lane = threadIdx.x & 31;

    if (bu == 0 && threadIdx.x == 0) *out = 0.0f;

    if (w == 1 && u >= UU - 1) return;
    int v = (w == 1) ? targets[b * (UU - 1) + u] : 0;

    const float* base = h + (size_t)b * TT * UU * VV + (size_t)u * VV + v;

    float x[7];
#pragma unroll
    for (int i = 0; i < 7; ++i) {
        int t = lane + 32 * i;
        x[i] = (t < TT) ? base[(size_t)t * (UU * VV)] * INV_LN2 : NEG_INF;
    }

    float m = x[0];
#pragma unroll
    for (int i = 1; i < 7; ++i) m = fmaxf(m, x[i]);
#pragma unroll
    for (int o = 16; o > 0; o >>= 1) m = fmaxf(m, __shfl_xor_sync(0xffffffffu, m, o));

    float s = 0.0f;
#pragma unroll
    for (int i = 0; i < 7; ++i) s += ex2f(x[i] - m);
#pragma unroll
    for (int o = 16; o > 0; o >>= 1) s += __shfl_xor_sync(0xffffffffu, s, o);

    float lse = m + lg2f(s);

    float* dst = (w == 0) ? (g_blank + (b * UU + u) * TT)
                          : (g_emit  + (b * (UU - 1) + u) * TT);
#pragma unroll
    for (int i = 0; i < 7; ++i) {
        int t = lane + 32 * i;
        if (t < TT) dst[t] = x[i] - lse;
    }
}

// ---------------------------------------------------------------------------
// Phase 2: single-warp wavefront per batch. Lane k owns col k (slot A) and
// col 32+k (slot B, lagged 32 steps). Sentinel-padded rows -> branchless,
// clampless, select-free steady-state body; all LDS offsets advance by +1/step.
// ---------------------------------------------------------------------------
__global__ void __launch_bounds__(256)
rnnt_dp_kernel(const int* __restrict__ input_lens,
               const int* __restrict__ target_lens,
               float* __restrict__ out) {
    extern __shared__ float sm[];
    float* sb    = sm;                         // blank rows [0,50)
    float* se    = sm + UU * RW;               // emit rows  [0,49)
    float* dummy = sm + (UU + UU - 1) * RW;    // all-sentinel row

    int b = blockIdx.x;
    int tid = threadIdx.x;

    // Fill entire region with sentinel, then overwrite data regions.
    for (int i = tid; i < NROWS * RW; i += 256) sm[i] = SENT;
    __syncthreads();
    {
        const float* srcb = g_blank + b * (UU * TT);
        const float* srce = g_emit  + b * ((UU - 1) * TT);
#pragma unroll 4
        for (int i = tid; i < UU * TT; i += 256) {
            int u = i / TT, t = i - u * TT;
            sb[u * RW + FRONT + t] = srcb[i];
        }
#pragma unroll 4
        for (int i = tid; i < (UU - 1) * TT; i += 256) {
            int u = i / TT, t = i - u * TT;
            se[u * RW + FRONT + t] = srce[i];
        }
    }
    __syncthreads();
    if (tid >= 32) return;

    int ti = input_lens[b] - 1;     // >= 99
    int ui = target_lens[b] - 1;    // >= 24

    int k = tid;
    int jB = 32 + k;
    int srcLane = (k + 31) & 31;

    // Base pointers; adding d gives the correct element each step.
    const float* pAb = sb + k * RW + (FRONT - k - 1);                         // blank[k][tA-1]
    const float* pAe = ((k > 0) ? se + (k - 1) * RW : dummy) + (FRONT - k);   // emit[k-1][tA]
    const float* pBb = ((jB < UU) ? sb + jB * RW       : dummy) + (FRONT - k - 33); // blank[jB][tB-1]
    const float* pBe = ((jB < UU) ? se + (jB - 1) * RW : dummy) + (FRONT - k - 32); // emit[jB-1][tB]

    // Capture steps (d at which this lane's slot produces alpha[ti][ui]).
    int dA = (k  == ui) ? ti + k       : -1;
    int dB = (jB == ui) ? ti + 32 + k  : -1;

    float own0 = (k == 0) ? 0.0f : SENT;   // alpha[0][0] seeded; loop starts d=1
    float own1 = SENT;
    float fin = 0.0f;

#pragma unroll 8
    for (int d = 1; d <= TT + UU - 2; ++d) {
        float prevA = __shfl_sync(0xffffffffu, own0, srcLane);
        float prevB = __shfl_sync(0xffffffffu, own1, srcLane);

        float xA = own0  + pAb[d];
        float yA = prevA + pAe[d];
        float nA = logadd2(xA, yA);

        float xB = own1  + pBb[d];
        float yB = prevB + pBe[d];
        float nB = logadd2(xB, yB);

        fin = (d == dA) ? nA : fin;
        fin = (d == dB) ? nB : fin;

        own0 = nA;
        own1 = (k == 31) ? nA : nB;   // lane 31 mirrors col 31 -> lane 0's prevB = col 31
    }

    bool holds = (k == ui) || (jB == ui);
    if (holds) {
        float loss2 = fin + sb[ui * RW + FRONT + ti];
        atomicAdd(out, -loss2 * LN2 * (1.0f / BB));
    }
}

// ---------------------------------------------------------------------------
extern "C" void kernel_launch(void* const* d_in, const int* in_sizes, int n_in,
                              void* d_out, int out_size) {
    const float* h           = (const float*)d_in[0];
    const int*   targets     = (const int*)d_in[1];
    const int*   input_lens  = (const int*)d_in[2];
    const int*   target_lens = (const int*)d_in[3];
    float* out = (float*)d_out;

    size_t smem = (size_t)NROWS * RW * sizeof(float);   // 125,200 B
    cudaFuncSetAttribute(rnnt_dp_kernel,
                         cudaFuncAttributeMaxDynamicSharedMemorySize, (int)smem);

    lse_gather_kernel<<<BB * UU, 64>>>(h, targets, out);
    rnnt_dp_kernel<<<BB, 256, smem>>>(input_lens, target_lens, out);
}